// round 1
// baseline (speedup 1.0000x reference)
#include <cuda_runtime.h>

#define LOG2E 1.4426950408889634f

// Scratch (allocation-free rule: __device__ globals)
__device__ float g_fused[32 * 2304];   // [sentence | scene_ctx | speaker_ctx]
__device__ float g_final[32 * 3840];   // [z | sentence_sh | scene_sh | speaker_sh]
__device__ float g_h[32 * 256];

__device__ __forceinline__ float ex2f(float x) {
    float y;
    asm("ex2.approx.f32 %0, %1;" : "=f"(y) : "f"(x));
    return y;
}

// ---------------------------------------------------------------------------
// Kernel 1: the two S=768 attentions + sentence copy, writing into g_fused.
// task 0: speaker_ctx = attn(q=oth, k=ts, v=ts)   -> g_fused[b][1536 + s]
// task 1: scene_ctx   = attn(q=ss,  k=ss, v=sd)   -> g_fused[b][ 768 + s]
// task 2: copy sentence                           -> g_fused[b][       s]
// grid (3, 32, 3), block 256
// ---------------------------------------------------------------------------
__global__ void attn_pre_kernel(const float* __restrict__ sent,
                                const float* __restrict__ ts,
                                const float* __restrict__ oth,
                                const float* __restrict__ sd,
                                const float* __restrict__ ss) {
    const int b    = blockIdx.y;
    const int task = blockIdx.z;
    const int s    = blockIdx.x * 256 + threadIdx.x;   // 0..767

    if (task == 2) {
        g_fused[b * 2304 + s] = sent[b * 768 + s];
        return;
    }

    const float* q = (task == 0) ? oth : ss;
    const float* k = (task == 0) ? ts  : ss;
    const float* v = (task == 0) ? ts  : sd;
    const int outoff = (task == 0) ? 1536 : 768;

    __shared__ __align__(16) float sk[768];
    __shared__ __align__(16) float sv[768];
    __shared__ float rmax[8], rmin[8];

    float lmax = -1e30f, lmin = 1e30f;
    for (int t = threadIdx.x; t < 768; t += 256) {
        float kv = k[b * 768 + t];
        sk[t] = kv;
        sv[t] = v[b * 768 + t];
        lmax = fmaxf(lmax, kv);
        lmin = fminf(lmin, kv);
    }
#pragma unroll
    for (int o = 16; o > 0; o >>= 1) {
        lmax = fmaxf(lmax, __shfl_xor_sync(0xffffffffu, lmax, o));
        lmin = fminf(lmin, __shfl_xor_sync(0xffffffffu, lmin, o));
    }
    if ((threadIdx.x & 31) == 0) {
        rmax[threadIdx.x >> 5] = lmax;
        rmin[threadIdx.x >> 5] = lmin;
    }
    __syncthreads();
    float kmax = rmax[0], kmin = rmin[0];
#pragma unroll
    for (int i = 1; i < 8; i++) {
        kmax = fmaxf(kmax, rmax[i]);
        kmin = fminf(kmin, rmin[i]);
    }

    const float qs  = q[b * 768 + s];
    const float m   = (qs >= 0.f) ? qs * kmax : qs * kmin;  // exact row max
    const float ql  = qs * LOG2E;
    const float nml = -m * LOG2E;

    float num = 0.f, den = 0.f;
    for (int t = 0; t < 768; t += 4) {
        float4 kk = *reinterpret_cast<const float4*>(sk + t);
        float4 vv = *reinterpret_cast<const float4*>(sv + t);
        float w0 = ex2f(fmaf(ql, kk.x, nml));
        float w1 = ex2f(fmaf(ql, kk.y, nml));
        float w2 = ex2f(fmaf(ql, kk.z, nml));
        float w3 = ex2f(fmaf(ql, kk.w, nml));
        num = fmaf(w0, vv.x, num); den += w0;
        num = fmaf(w1, vv.y, num); den += w1;
        num = fmaf(w2, vv.z, num); den += w2;
        num = fmaf(w3, vv.w, num); den += w3;
    }
    g_fused[b * 2304 + outoff + s] = num / den;
}

// ---------------------------------------------------------------------------
// Kernel 2: fused self-attention, S=2304, q=k=v=g_fused[b].
// z -> g_final[b][0..2303].  grid (9, 32), block 256
// ---------------------------------------------------------------------------
__global__ void attn_fused_kernel() {
    const int b = blockIdx.y;
    const int s = blockIdx.x * 256 + threadIdx.x;   // 0..2303

    __shared__ __align__(16) float sf[2304];
    __shared__ float rmax[8], rmin[8];

    float lmax = -1e30f, lmin = 1e30f;
    for (int t = threadIdx.x; t < 2304; t += 256) {
        float fv = g_fused[b * 2304 + t];
        sf[t] = fv;
        lmax = fmaxf(lmax, fv);
        lmin = fminf(lmin, fv);
    }
#pragma unroll
    for (int o = 16; o > 0; o >>= 1) {
        lmax = fmaxf(lmax, __shfl_xor_sync(0xffffffffu, lmax, o));
        lmin = fminf(lmin, __shfl_xor_sync(0xffffffffu, lmin, o));
    }
    if ((threadIdx.x & 31) == 0) {
        rmax[threadIdx.x >> 5] = lmax;
        rmin[threadIdx.x >> 5] = lmin;
    }
    __syncthreads();
    float kmax = rmax[0], kmin = rmin[0];
#pragma unroll
    for (int i = 1; i < 8; i++) {
        kmax = fmaxf(kmax, rmax[i]);
        kmin = fminf(kmin, rmin[i]);
    }

    const float qs  = sf[s];
    const float m   = (qs >= 0.f) ? qs * kmax : qs * kmin;
    const float ql  = qs * LOG2E;
    const float nml = -m * LOG2E;

    float num = 0.f, den = 0.f;
    for (int t = 0; t < 2304; t += 4) {
        float4 kk = *reinterpret_cast<const float4*>(sf + t);  // k == v here
        float w0 = ex2f(fmaf(ql, kk.x, nml));
        float w1 = ex2f(fmaf(ql, kk.y, nml));
        float w2 = ex2f(fmaf(ql, kk.z, nml));
        float w3 = ex2f(fmaf(ql, kk.w, nml));
        num = fmaf(w0, kk.x, num); den += w0;
        num = fmaf(w1, kk.y, num); den += w1;
        num = fmaf(w2, kk.z, num); den += w2;
        num = fmaf(w3, kk.w, num); den += w3;
    }
    g_final[b * 3840 + s] = num / den;
}

// ---------------------------------------------------------------------------
// Kernel 3: three shared projections X @ W_shared + b_shared.
// task 0: X=sentence      -> g_final[b][2304 + n]
// task 1: X=scene_ctx     -> g_final[b][2816 + n]
// task 2: X=speaker_ctx   -> g_final[b][3328 + n]
// grid (4, 32, 3), block 128
// ---------------------------------------------------------------------------
__global__ void shared_proj_kernel(const float* __restrict__ sent,
                                   const float* __restrict__ Wsh,
                                   const float* __restrict__ bsh) {
    const int b    = blockIdx.y;
    const int task = blockIdx.z;
    const int n    = blockIdx.x * 128 + threadIdx.x;   // 0..511

    __shared__ float xs[768];
    const float* X = (task == 0) ? (sent + b * 768)
                                 : (g_fused + b * 2304 + 768 * task);
    for (int d = threadIdx.x; d < 768; d += 128) xs[d] = X[d];
    __syncthreads();

    float a0 = bsh[n], a1 = 0.f, a2 = 0.f, a3 = 0.f;
    for (int d = 0; d < 768; d += 4) {
        a0 = fmaf(xs[d + 0], Wsh[(d + 0) * 512 + n], a0);
        a1 = fmaf(xs[d + 1], Wsh[(d + 1) * 512 + n], a1);
        a2 = fmaf(xs[d + 2], Wsh[(d + 2) * 512 + n], a2);
        a3 = fmaf(xs[d + 3], Wsh[(d + 3) * 512 + n], a3);
    }
    g_final[b * 3840 + 2304 + task * 512 + n] = (a0 + a1) + (a2 + a3);
}

// ---------------------------------------------------------------------------
// Kernel 4: h = relu(final @ W1 + b1).  grid (2, 32), block 128
// ---------------------------------------------------------------------------
__global__ void mlp1_kernel(const float* __restrict__ W1,
                            const float* __restrict__ b1) {
    const int b = blockIdx.y;
    const int j = blockIdx.x * 128 + threadIdx.x;   // 0..255

    __shared__ float xs[3840];
    for (int i = threadIdx.x; i < 3840; i += 128) xs[i] = g_final[b * 3840 + i];
    __syncthreads();

    float a0 = b1[j], a1 = 0.f, a2 = 0.f, a3 = 0.f;
    for (int i = 0; i < 3840; i += 4) {
        a0 = fmaf(xs[i + 0], W1[(i + 0) * 256 + j], a0);
        a1 = fmaf(xs[i + 1], W1[(i + 1) * 256 + j], a1);
        a2 = fmaf(xs[i + 2], W1[(i + 2) * 256 + j], a2);
        a3 = fmaf(xs[i + 3], W1[(i + 3) * 256 + j], a3);
    }
    float acc = (a0 + a1) + (a2 + a3);
    g_h[b * 256 + j] = fmaxf(acc, 0.f);
}

// ---------------------------------------------------------------------------
// Kernel 5: out = sigmoid(h @ W2 + b2).  grid 1, block 256 (224 active)
// ---------------------------------------------------------------------------
__global__ void mlp2_kernel(const float* __restrict__ W2,
                            const float* __restrict__ b2,
                            float* __restrict__ out) {
    const int tid = threadIdx.x;
    if (tid >= 224) return;
    const int b = tid / 7, c = tid % 7;

    float a0 = b2[c], a1 = 0.f, a2 = 0.f, a3 = 0.f;
    for (int j = 0; j < 256; j += 4) {
        a0 = fmaf(g_h[b * 256 + j + 0], W2[(j + 0) * 7 + c], a0);
        a1 = fmaf(g_h[b * 256 + j + 1], W2[(j + 1) * 7 + c], a1);
        a2 = fmaf(g_h[b * 256 + j + 2], W2[(j + 2) * 7 + c], a2);
        a3 = fmaf(g_h[b * 256 + j + 3], W2[(j + 3) * 7 + c], a3);
    }
    float x = (a0 + a1) + (a2 + a3);
    out[b * 7 + c] = 1.f / (1.f + __expf(-x));
}

extern "C" void kernel_launch(void* const* d_in, const int* in_sizes, int n_in,
                              void* d_out, int out_size) {
    const float* sent = (const float*)d_in[0];
    const float* ts   = (const float*)d_in[1];
    const float* oth  = (const float*)d_in[2];
    const float* sd   = (const float*)d_in[3];
    const float* ss   = (const float*)d_in[4];
    const float* Wsh  = (const float*)d_in[5];
    const float* bsh  = (const float*)d_in[6];
    const float* W1   = (const float*)d_in[7];
    const float* b1   = (const float*)d_in[8];
    const float* W2   = (const float*)d_in[9];
    const float* b2   = (const float*)d_in[10];
    float* out = (float*)d_out;

    attn_pre_kernel<<<dim3(3, 32, 3), 256>>>(sent, ts, oth, sd, ss);
    shared_proj_kernel<<<dim3(4, 32, 3), 128>>>(sent, Wsh, bsh);
    attn_fused_kernel<<<dim3(9, 32), 256>>>();
    mlp1_kernel<<<dim3(2, 32), 128>>>(W1, b1);
    mlp2_kernel<<<1, 256>>>(W2, b2, out);
}

// round 2
// speedup vs baseline: 1.8440x; 1.8440x over previous
#include <cuda_runtime.h>

#define LOG2E 1.4426950408889634f

// ---------------- scratch (__device__ globals; allocation-free rule) -------
__device__ float g_fused[32 * 2304];   // [sentence | scene_ctx | speaker_ctx]
__device__ float g_final[32 * 3840];   // [z | sentence_sh | scene_sh | speaker_sh]
__device__ float g_h[32 * 256];

// split-K partial buffers
#define PROJ_KC 24      // 768 / 32
#define PROJ_KCH 32
#define MLP_KC 120      // 3840 / 32
#define MLP_KCH 32
__device__ float g_pp[3 * PROJ_KC * 32 * 512];   // proj partials
__device__ float g_pm[MLP_KC * 32 * 256];        // mlp1 partials

__device__ __forceinline__ float ex2f(float x) {
    float y;
    asm("ex2.approx.f32 %0, %1;" : "=f"(y) : "f"(x));
    return y;
}

// ---------------------------------------------------------------------------
// Kernel 1: the two S=768 attentions + sentence copy, writing into g_fused.
// task 0: speaker_ctx = attn(q=oth, k=ts, v=ts)   -> g_fused[b][1536 + s]
// task 1: scene_ctx   = attn(q=ss,  k=ss, v=sd)   -> g_fused[b][ 768 + s]
// task 2: copy sentence                           -> g_fused[b][       s]
// grid (3, 32, 3), block 256
// ---------------------------------------------------------------------------
__global__ void attn_pre_kernel(const float* __restrict__ sent,
                                const float* __restrict__ ts,
                                const float* __restrict__ oth,
                                const float* __restrict__ sd,
                                const float* __restrict__ ss) {
    const int b    = blockIdx.y;
    const int task = blockIdx.z;
    const int s    = blockIdx.x * 256 + threadIdx.x;   // 0..767

    if (task == 2) {
        g_fused[b * 2304 + s] = sent[b * 768 + s];
        return;
    }

    const float* q = (task == 0) ? oth : ss;
    const float* k = (task == 0) ? ts  : ss;
    const float* v = (task == 0) ? ts  : sd;
    const int outoff = (task == 0) ? 1536 : 768;

    __shared__ __align__(16) float sk[768];
    __shared__ __align__(16) float sv[768];
    __shared__ float rmax[8], rmin[8];

    float lmax = -1e30f, lmin = 1e30f;
    for (int t = threadIdx.x; t < 768; t += 256) {
        float kv = k[b * 768 + t];
        sk[t] = kv;
        sv[t] = v[b * 768 + t];
        lmax = fmaxf(lmax, kv);
        lmin = fminf(lmin, kv);
    }
#pragma unroll
    for (int o = 16; o > 0; o >>= 1) {
        lmax = fmaxf(lmax, __shfl_xor_sync(0xffffffffu, lmax, o));
        lmin = fminf(lmin, __shfl_xor_sync(0xffffffffu, lmin, o));
    }
    if ((threadIdx.x & 31) == 0) {
        rmax[threadIdx.x >> 5] = lmax;
        rmin[threadIdx.x >> 5] = lmin;
    }
    __syncthreads();
    float kmax = rmax[0], kmin = rmin[0];
#pragma unroll
    for (int i = 1; i < 8; i++) {
        kmax = fmaxf(kmax, rmax[i]);
        kmin = fminf(kmin, rmin[i]);
    }

    const float qs  = q[b * 768 + s];
    const float m   = (qs >= 0.f) ? qs * kmax : qs * kmin;  // exact row max
    const float ql  = qs * LOG2E;
    const float nml = -m * LOG2E;

    float num = 0.f, den = 0.f;
    for (int t = 0; t < 768; t += 4) {
        float4 kk = *reinterpret_cast<const float4*>(sk + t);
        float4 vv = *reinterpret_cast<const float4*>(sv + t);
        float w0 = ex2f(fmaf(ql, kk.x, nml));
        float w1 = ex2f(fmaf(ql, kk.y, nml));
        float w2 = ex2f(fmaf(ql, kk.z, nml));
        float w3 = ex2f(fmaf(ql, kk.w, nml));
        num = fmaf(w0, vv.x, num); den += w0;
        num = fmaf(w1, vv.y, num); den += w1;
        num = fmaf(w2, vv.z, num); den += w2;
        num = fmaf(w3, vv.w, num); den += w3;
    }
    g_fused[b * 2304 + outoff + s] = num / den;
}

// ---------------------------------------------------------------------------
// Kernel 2: fused self-attention, S=2304, q=k=v=g_fused[b].
// z -> g_final[b][0..2303].  grid (9, 32), block 256
// ---------------------------------------------------------------------------
__global__ void attn_fused_kernel() {
    const int b = blockIdx.y;
    const int s = blockIdx.x * 256 + threadIdx.x;   // 0..2303

    __shared__ __align__(16) float sf[2304];
    __shared__ float rmax[8], rmin[8];

    float lmax = -1e30f, lmin = 1e30f;
    for (int t = threadIdx.x; t < 2304; t += 256) {
        float fv = g_fused[b * 2304 + t];
        sf[t] = fv;
        lmax = fmaxf(lmax, fv);
        lmin = fminf(lmin, fv);
    }
#pragma unroll
    for (int o = 16; o > 0; o >>= 1) {
        lmax = fmaxf(lmax, __shfl_xor_sync(0xffffffffu, lmax, o));
        lmin = fminf(lmin, __shfl_xor_sync(0xffffffffu, lmin, o));
    }
    if ((threadIdx.x & 31) == 0) {
        rmax[threadIdx.x >> 5] = lmax;
        rmin[threadIdx.x >> 5] = lmin;
    }
    __syncthreads();
    float kmax = rmax[0], kmin = rmin[0];
#pragma unroll
    for (int i = 1; i < 8; i++) {
        kmax = fmaxf(kmax, rmax[i]);
        kmin = fminf(kmin, rmin[i]);
    }

    const float qs  = sf[s];
    const float m   = (qs >= 0.f) ? qs * kmax : qs * kmin;
    const float ql  = qs * LOG2E;
    const float nml = -m * LOG2E;

    float num = 0.f, den = 0.f;
    for (int t = 0; t < 2304; t += 4) {
        float4 kk = *reinterpret_cast<const float4*>(sf + t);  // k == v here
        float w0 = ex2f(fmaf(ql, kk.x, nml));
        float w1 = ex2f(fmaf(ql, kk.y, nml));
        float w2 = ex2f(fmaf(ql, kk.z, nml));
        float w3 = ex2f(fmaf(ql, kk.w, nml));
        num = fmaf(w0, kk.x, num); den += w0;
        num = fmaf(w1, kk.y, num); den += w1;
        num = fmaf(w2, kk.z, num); den += w2;
        num = fmaf(w3, kk.w, num); den += w3;
    }
    g_final[b * 3840 + s] = num / den;
}

// ---------------------------------------------------------------------------
// Kernel 3a: split-K shared projections.
// grid (PROJ_KC, 4, 3) = (kchunk, jtile, task), block 128 (j within tile).
// Each block: K-chunk of 32, all 32 batches, 128 output cols.
// W element loaded once -> 32 FMAs (register accs) -> latency hidden.
// ---------------------------------------------------------------------------
__global__ void shared_proj_split(const float* __restrict__ sent,
                                  const float* __restrict__ Wsh) {
    const int kc   = blockIdx.x;
    const int jt   = blockIdx.y;
    const int task = blockIdx.z;
    const int j    = jt * 128 + threadIdx.x;      // 0..511
    const int i0   = kc * PROJ_KCH;

    __shared__ __align__(16) float xs[PROJ_KCH][36];  // [i][b], padded

    // coalesced load: warp reads 32 consecutive i for one b
    for (int e = threadIdx.x; e < PROJ_KCH * 32; e += 128) {
        int b = e >> 5, i = e & 31;
        float v = (task == 0) ? sent[b * 768 + i0 + i]
                              : g_fused[b * 2304 + 768 * task + i0 + i];
        xs[i][b] = v;
    }
    __syncthreads();

    float acc[32];
#pragma unroll
    for (int b = 0; b < 32; b++) acc[b] = 0.f;

    for (int i = 0; i < PROJ_KCH; i++) {
        float w = Wsh[(i0 + i) * 512 + j];
#pragma unroll
        for (int b4 = 0; b4 < 8; b4++) {
            float4 x = *reinterpret_cast<const float4*>(&xs[i][b4 * 4]);
            acc[b4 * 4 + 0] = fmaf(x.x, w, acc[b4 * 4 + 0]);
            acc[b4 * 4 + 1] = fmaf(x.y, w, acc[b4 * 4 + 1]);
            acc[b4 * 4 + 2] = fmaf(x.z, w, acc[b4 * 4 + 2]);
            acc[b4 * 4 + 3] = fmaf(x.w, w, acc[b4 * 4 + 3]);
        }
    }

#pragma unroll
    for (int b = 0; b < 32; b++)
        g_pp[(((task * PROJ_KC) + kc) * 32 + b) * 512 + j] = acc[b];
}

// Kernel 3b: reduce proj partials + bias -> g_final.  grid 192, block 256
__global__ void proj_reduce(const float* __restrict__ bsh) {
    const int o = blockIdx.x * 256 + threadIdx.x;   // 0..49151
    const int task = o >> 14;           // /(32*512)
    const int r = o & 16383;
    const int b = r >> 9;
    const int j = r & 511;

    float a0 = bsh[j], a1 = 0.f, a2 = 0.f, a3 = 0.f;
#pragma unroll
    for (int kc = 0; kc < PROJ_KC; kc += 4) {
        a0 += g_pp[(((task * PROJ_KC) + kc + 0) * 32 + b) * 512 + j];
        a1 += g_pp[(((task * PROJ_KC) + kc + 1) * 32 + b) * 512 + j];
        a2 += g_pp[(((task * PROJ_KC) + kc + 2) * 32 + b) * 512 + j];
        a3 += g_pp[(((task * PROJ_KC) + kc + 3) * 32 + b) * 512 + j];
    }
    g_final[b * 3840 + 2304 + task * 512 + j] = (a0 + a1) + (a2 + a3);
}

// ---------------------------------------------------------------------------
// Kernel 4a: split-K mlp1.  grid (MLP_KC), block 256 (j = tid).
// ---------------------------------------------------------------------------
__global__ void mlp1_split(const float* __restrict__ W1) {
    const int kc = blockIdx.x;
    const int i0 = kc * MLP_KCH;
    const int j  = threadIdx.x;   // 0..255

    __shared__ __align__(16) float xs[MLP_KCH][36];

    for (int e = threadIdx.x; e < MLP_KCH * 32; e += 256) {
        int b = e >> 5, i = e & 31;
        xs[i][b] = g_final[b * 3840 + i0 + i];
    }
    __syncthreads();

    float acc[32];
#pragma unroll
    for (int b = 0; b < 32; b++) acc[b] = 0.f;

    for (int i = 0; i < MLP_KCH; i++) {
        float w = W1[(i0 + i) * 256 + j];
#pragma unroll
        for (int b4 = 0; b4 < 8; b4++) {
            float4 x = *reinterpret_cast<const float4*>(&xs[i][b4 * 4]);
            acc[b4 * 4 + 0] = fmaf(x.x, w, acc[b4 * 4 + 0]);
            acc[b4 * 4 + 1] = fmaf(x.y, w, acc[b4 * 4 + 1]);
            acc[b4 * 4 + 2] = fmaf(x.z, w, acc[b4 * 4 + 2]);
            acc[b4 * 4 + 3] = fmaf(x.w, w, acc[b4 * 4 + 3]);
        }
    }

#pragma unroll
    for (int b = 0; b < 32; b++)
        g_pm[(kc * 32 + b) * 256 + j] = acc[b];
}

// Kernel 4b: reduce mlp1 partials + bias + relu -> g_h.  grid 32, block 256
__global__ void mlp1_reduce(const float* __restrict__ b1) {
    const int o = blockIdx.x * 256 + threadIdx.x;   // 0..8191
    const int b = o >> 8;
    const int j = o & 255;

    float a0 = b1[j], a1 = 0.f, a2 = 0.f, a3 = 0.f;
#pragma unroll
    for (int kc = 0; kc < MLP_KC; kc += 4) {
        a0 += g_pm[((kc + 0) * 32 + b) * 256 + j];
        a1 += g_pm[((kc + 1) * 32 + b) * 256 + j];
        a2 += g_pm[((kc + 2) * 32 + b) * 256 + j];
        a3 += g_pm[((kc + 3) * 32 + b) * 256 + j];
    }
    g_h[o] = fmaxf((a0 + a1) + (a2 + a3), 0.f);
}

// ---------------------------------------------------------------------------
// Kernel 5: out = sigmoid(h @ W2 + b2).  grid 1, block 256 (224 active)
// ---------------------------------------------------------------------------
__global__ void mlp2_kernel(const float* __restrict__ W2,
                            const float* __restrict__ b2,
                            float* __restrict__ out) {
    const int tid = threadIdx.x;
    if (tid >= 224) return;
    const int b = tid / 7, c = tid % 7;

    float a0 = b2[c], a1 = 0.f, a2 = 0.f, a3 = 0.f;
    for (int jj = 0; jj < 256; jj += 4) {
        a0 = fmaf(g_h[b * 256 + jj + 0], W2[(jj + 0) * 7 + c], a0);
        a1 = fmaf(g_h[b * 256 + jj + 1], W2[(jj + 1) * 7 + c], a1);
        a2 = fmaf(g_h[b * 256 + jj + 2], W2[(jj + 2) * 7 + c], a2);
        a3 = fmaf(g_h[b * 256 + jj + 3], W2[(jj + 3) * 7 + c], a3);
    }
    float x = (a0 + a1) + (a2 + a3);
    out[b * 7 + c] = 1.f / (1.f + __expf(-x));
}

extern "C" void kernel_launch(void* const* d_in, const int* in_sizes, int n_in,
                              void* d_out, int out_size) {
    const float* sent = (const float*)d_in[0];
    const float* ts   = (const float*)d_in[1];
    const float* oth  = (const float*)d_in[2];
    const float* sd   = (const float*)d_in[3];
    const float* ss   = (const float*)d_in[4];
    const float* Wsh  = (const float*)d_in[5];
    const float* bsh  = (const float*)d_in[6];
    const float* W1   = (const float*)d_in[7];
    const float* b1   = (const float*)d_in[8];
    const float* W2   = (const float*)d_in[9];
    const float* b2   = (const float*)d_in[10];
    float* out = (float*)d_out;

    attn_pre_kernel<<<dim3(3, 32, 3), 256>>>(sent, ts, oth, sd, ss);
    shared_proj_split<<<dim3(PROJ_KC, 4, 3), 128>>>(sent, Wsh);
    proj_reduce<<<192, 256>>>(bsh);
    attn_fused_kernel<<<dim3(9, 32), 256>>>();
    mlp1_split<<<MLP_KC, 256>>>(W1);
    mlp1_reduce<<<32, 256>>>(b1);
    mlp2_kernel<<<1, 256>>>(W2, b2, out);
}